// round 12
// baseline (speedup 1.0000x reference)
#include <cuda_runtime.h>
#include <cuda_bf16.h>
#include <cstdint>

#define DINLINE __device__ __forceinline__

// ---------------- problem sizes ----------------
#define B_  64
#define TN_ 131072
#define TE_ 262144
#define TT_ (TN_ + TE_)
#define QD_ 768
#define PD_ 512
#define KD_ 512

// ---------------- device scratch ----------------
__device__ float g_qn[B_ * PD_];
__device__ float g_qe[B_ * PD_];
__device__ __nv_bfloat16 g_wtn[PD_ * KD_];   // W_n transposed [P][K], bf16
__device__ __nv_bfloat16 g_wte[PD_ * KD_];
__device__ float g_part[4 * TT_];            // per-N-slice partial sums (no init needed)
__device__ float g_e[TT_];                   // exp(score)
__device__ float g_sum[128];                 // per-graph exp sums (0..63 nodes, 64..127 edges)

// ---------------- helpers ----------------
DINLINE void cp16(uint32_t s, const void* g) {
    asm volatile("cp.async.cg.shared.global [%0], [%1], 16;"
                 :: "r"(s), "l"(g) : "memory");
}
DINLINE void cp_commit() { asm volatile("cp.async.commit_group;" ::: "memory"); }
template<int N> DINLINE void cp_wait() {
    asm volatile("cp.async.wait_group %0;" :: "n"(N) : "memory");
}

DINLINE uint32_t smem_u32(const void* p) {
    uint32_t a;
    asm("{ .reg .u64 t; cvta.to.shared.u64 t, %1; cvt.u32.u64 %0, t; }"
        : "=r"(a) : "l"(p));
    return a;
}

DINLINE float tanh_fast(float x) {
    float y;
    asm("tanh.approx.f32 %0, %1;" : "=f"(y) : "f"(x));
    return y;
}

DINLINE void mma_bf16(float* c, const uint32_t* a, const uint32_t* b) {
    asm volatile(
        "mma.sync.aligned.m16n8k16.row.col.f32.bf16.bf16.f32 "
        "{%0,%1,%2,%3}, {%4,%5,%6,%7}, {%8,%9}, {%0,%1,%2,%3};"
        : "+f"(c[0]), "+f"(c[1]), "+f"(c[2]), "+f"(c[3])
        : "r"(a[0]), "r"(a[1]), "r"(a[2]), "r"(a[3]),
          "r"(b[0]), "r"(b[1]));
}

DINLINE void ldm_x4(uint32_t& r0, uint32_t& r1, uint32_t& r2, uint32_t& r3,
                    uint32_t addr) {
    asm volatile("ldmatrix.sync.aligned.m8n8.x4.shared.b16 {%0,%1,%2,%3}, [%4];"
                 : "=r"(r0), "=r"(r1), "=r"(r2), "=r"(r3) : "r"(addr));
}

DINLINE uint32_t pack_bf16x2(float lo, float hi) {
    __nv_bfloat162 v = __float22bfloat162_rn(make_float2(lo, hi));
    return *reinterpret_cast<uint32_t*>(&v);
}

// ---------------- main fused GEMM ----------------
// CTA: 256 threads (8 warps, 4 wm x 2 wn, warp tile 64x64).
// Tile: M=256, N=128 (blockIdx.x in 0..3), K=512 in 16 chunks of 32.
// blockIdx.y in [0,1536): y<512 -> nodes; else edges.
// SMEM (bf16, 80B padded rows):
//   A: 2 x (256 x 80B = 20480)  @ 0
//   B: 3 x (128 x 80B = 10240)  @ 40960
//   s_sm: 256 floats            @ 71680
#define ROWB   80u
#define ATILE  20480u
#define BTILE  10240u
#define BOFF   40960u
#define SM_OFF 71680u
#define SMEM_BYTES (71680 + 1024)
#define NYN 512              // node tiles in y

__global__ void __launch_bounds__(256, 1) k_main(
    const float* __restrict__ An, const float* __restrict__ Ae,
    const int* __restrict__ gidN, const int* __restrict__ gidE,
    const __nv_bfloat16* __restrict__ WtN, const __nv_bfloat16* __restrict__ WtE,
    const float* __restrict__ qN, const float* __restrict__ qE,
    const float* __restrict__ wvN, const float* __restrict__ wvE,
    float* __restrict__ part)
{
    extern __shared__ char smem[];
    float* s_sm = reinterpret_cast<float*>(smem + SM_OFF);

    const bool isNode = blockIdx.y < NYN;
    const int  ty     = isNode ? blockIdx.y : blockIdx.y - NYN;
    const float* __restrict__ A    = isNode ? An   : Ae;
    const int*   __restrict__ gid  = isNode ? gidN : gidE;
    const __nv_bfloat16* __restrict__ Wt = isNode ? WtN : WtE;
    const float* __restrict__ qeff = isNode ? qN   : qE;
    const float* __restrict__ wv   = isNode ? wvN  : wvE;
    const int    sOff = isNode ? 0 : TN_;

    const int tid  = threadIdx.x;
    const int lane = tid & 31;
    const int warp = tid >> 5;
    const int wm   = warp & 3;   // M block of 64
    const int wn   = warp >> 2;  // N block of 64

    const int mBase = ty * 256;
    const int nBase = blockIdx.x * 128;

    const uint32_t sb = smem_u32(smem);

    s_sm[tid] = 0.f;

    // ---- A loader: 256 rows x 32 f32 per chunk; thread: 8 float4
    const int aRow = tid >> 3;
    const int aQ   = tid & 7;
    const float* Abase = A + (size_t)(mBase + aRow) * KD_ + aQ * 4;

    float4 ra[8];
    auto ldA = [&](int kc) {
        const float* p = Abase + kc * 32;
#pragma unroll
        for (int i = 0; i < 8; ++i)
            ra[i] = *reinterpret_cast<const float4*>(p + (size_t)i * 32 * KD_);
    };
    auto stsA = [&](int buf) {
        const uint32_t base = sb + buf * ATILE + aRow * ROWB + aQ * 8;
#pragma unroll
        for (int i = 0; i < 8; ++i) {
            uint32_t lo = pack_bf16x2(ra[i].x, ra[i].y);
            uint32_t hi = pack_bf16x2(ra[i].z, ra[i].w);
            asm volatile("st.shared.v2.b32 [%0], {%1,%2};"
                         :: "r"(base + i * 32 * ROWB), "r"(lo), "r"(hi) : "memory");
        }
    };
    // B: 128 n-rows x 32 bf16 per chunk = 8KB = 512 x 16B; thread does 2 cp16
    const int bIdx0 = tid * 2;
    auto cpB = [&](int slot, int kc) {
#pragma unroll
        for (int j = 0; j < 2; ++j) {
            int idx = bIdx0 + j;
            int n = idx >> 2, g = idx & 3;
            cp16(sb + BOFF + slot * BTILE + n * ROWB + g * 16,
                 Wt + (size_t)(nBase + n) * KD_ + kc * 32 + g * 8);
        }
        cp_commit();
    };

    float c[4][8][4];
#pragma unroll
    for (int mt = 0; mt < 4; ++mt)
#pragma unroll
        for (int nt = 0; nt < 8; ++nt)
#pragma unroll
            for (int i = 0; i < 4; ++i) c[mt][nt][i] = 0.f;

    // ---- ldmatrix per-lane offsets ----
    const int j = lane >> 3;
    const uint32_t aLane = (uint32_t)(wm * 64 + ((j & 1) << 3) + (lane & 7)) * ROWB
                         + (uint32_t)(j >> 1) * 16u;
    const uint32_t bLane = (uint32_t)(wn * 64 + ((j >> 1) << 3) + (lane & 7)) * ROWB
                         + (uint32_t)(j & 1) * 16u;

    // ---- register-resident A fragment sets (ping-pong, no copies) ----
    uint32_t aF0[4][4], aF1[4][4];

    auto ldA_frags = [&](uint32_t aT2, uint32_t ko, uint32_t (&a)[4][4]) {
#pragma unroll
        for (int mt = 0; mt < 4; ++mt)
            ldm_x4(a[mt][0], a[mt][1], a[mt][2], a[mt][3],
                   aT2 + mt * 16 * ROWB + ko);
    };

    auto phase = [&](const uint32_t (&aIn)[4][4], uint32_t (&aOut)[4][4],
                     uint32_t bT2, uint32_t ko,
                     uint32_t aT2n, uint32_t kon, bool preloadA) {
        uint32_t b[2][2][2];   // [buf][nt-in-pair][frag]
        ldm_x4(b[0][0][0], b[0][0][1], b[0][1][0], b[0][1][1], bT2 + ko);
#pragma unroll
        for (int p = 0; p < 4; ++p) {
            const int cb = p & 1, nb = cb ^ 1;
            if (p < 3) {
                ldm_x4(b[nb][0][0], b[nb][0][1], b[nb][1][0], b[nb][1][1],
                       bT2 + (uint32_t)(p + 1) * 16 * ROWB + ko);
            } else if (preloadA) {
                ldA_frags(aT2n, kon, aOut);
            }
#pragma unroll
            for (int mt = 0; mt < 4; ++mt) {
                mma_bf16(c[mt][2 * p],     aIn[mt], b[cb][0]);
                mma_bf16(c[mt][2 * p + 1], aIn[mt], b[cb][1]);
            }
        }
    };

    // ---- preamble ----
    ldA(0);
    cpB(0, 0);
    cpB(1, 1);
    stsA(0);
    ldA(1);
    cp_wait<1>();
    __syncthreads();
    ldA_frags(sb + aLane, 0, aF0);     // chunk 0, ks=0

#pragma unroll 1
    for (int kc = 0; kc < 16; ++kc) {
        const int abuf = kc & 1;
        if (kc + 2 < 16) cpB((kc + 2) % 3, kc + 2);

        const uint32_t aT2 = sb + abuf * ATILE + aLane;
        const uint32_t bT2 = sb + BOFF + (kc % 3) * BTILE + bLane;

        phase(aF0, aF1, bT2, 0, aT2, 32, true);
        if (kc + 1 < 16) stsA(abuf ^ 1);
        if (kc + 2 < 16) ldA(kc + 2);
        phase(aF1, aF0, bT2, 32, 0, 0, false);

        if (kc + 2 < 16) cp_wait<1>(); else cp_wait<0>();
        __syncthreads();
        if (kc + 1 < 16)
            ldA_frags(sb + (abuf ^ 1) * ATILE + aLane, 0, aF0);
    }

    // ---- epilogue: partial s[m] for this N-slice; no global atomics ----
    const int n0 = wn * 64 + 2 * (lane & 3);
#pragma unroll
    for (int mt = 0; mt < 4; ++mt) {
#pragma unroll
        for (int h = 0; h < 2; ++h) {
            const int row = wm * 64 + mt * 16 + (lane >> 2) + h * 8;
            const int g = __ldg(gid + mBase + row);
            const float* qrow = qeff + (size_t)g * PD_ + nBase;
            float s = 0.f;
#pragma unroll
            for (int nt = 0; nt < 8; ++nt) {
                const int nn = n0 + nt * 8;
                float2 q2 = *reinterpret_cast<const float2*>(qrow + nn);
                float2 w2 = *reinterpret_cast<const float2*>(wv + nBase + nn);
                float x0 = tanh_fast(c[mt][nt][h * 2 + 0] + q2.x);
                float x1 = tanh_fast(c[mt][nt][h * 2 + 1] + q2.y);
                s = fmaf(x0, w2.x, s);
                s = fmaf(x1, w2.y, s);
            }
            s += __shfl_xor_sync(0xffffffffu, s, 1);
            s += __shfl_xor_sync(0xffffffffu, s, 2);
            if ((lane & 3) == 0) atomicAdd(&s_sm[row], s);
        }
    }
    __syncthreads();
    part[(size_t)blockIdx.x * TT_ + sOff + mBase + tid] = s_sm[tid];
}

// ---------------- prep: transposes + qn/qe/gsum zeroing, one launch ----------------
// grid 545 x 256 threads:
//   blk 0..255:   transpose W_n tile
//   blk 256..511: transpose W_e
//   blk 512..543: zero qn/qe
//   blk 544:      zero g_sum
__global__ void __launch_bounds__(256) k_prep(
    const float* __restrict__ Wn, const float* __restrict__ We,
    __nv_bfloat16* __restrict__ WtN, __nv_bfloat16* __restrict__ WtE,
    float* __restrict__ qn, float* __restrict__ qe, float* __restrict__ gsum) {
    const int blk = blockIdx.x;
    const int t = threadIdx.x;
    if (blk == 544) {
        if (t < 128) gsum[t] = 0.f;
        return;
    }
    if (blk >= 512) {
        const int zi = blk - 512;                 // 0..31
        float* dst = (zi < 16) ? (qn + zi * 2048) : (qe + (zi - 16) * 2048);
#pragma unroll
        for (int k = 0; k < 8; ++k) dst[k * 256 + t] = 0.f;
        return;
    }
    const bool isE = blk >= 256;
    const int b2 = blk & 255;
    const float* W = isE ? We : Wn;
    __nv_bfloat16* Wt = isE ? WtE : WtN;
    __shared__ float tile[32][33];
    const int tx = t & 31, ty2 = t >> 5;          // 32 x 8
    int x = (b2 & 15) * 32 + tx;                  // p
    int y = (b2 >> 4) * 32 + ty2;                 // k
#pragma unroll
    for (int j = 0; j < 32; j += 8)
        tile[ty2 + j][tx] = W[(y + j) * 512 + x];
    __syncthreads();
    int xo = (b2 >> 4) * 32 + tx;                 // k
    int yo = (b2 & 15) * 32 + ty2;                // p
#pragma unroll
    for (int j = 0; j < 32; j += 8)
        Wt[(yo + j) * 512 + xo] = __float2bfloat16(tile[tx][ty2 + j]);
}

// split-k qproj, grid (B_, 16, 2): k-slice 48; z selects node/edge weights.
__global__ void __launch_bounds__(256) k_qproj(
    const float* __restrict__ q,
    const float* __restrict__ WqN, const float* __restrict__ bqN, const float* __restrict__ bhN,
    const float* __restrict__ WqE, const float* __restrict__ bqE, const float* __restrict__ bhE,
    float* __restrict__ outN, float* __restrict__ outE) {
    const float* Wq = blockIdx.z ? WqE : WqN;
    const float* bq = blockIdx.z ? bqE : bqN;
    const float* bh = blockIdx.z ? bhE : bhN;
    float* out = blockIdx.z ? outE : outN;
    __shared__ float qs[48];
    const int b = blockIdx.x, ks = blockIdx.y;
    const int k0 = ks * 48;
    const int t = threadIdx.x;
    if (t < 48) qs[t] = q[b * QD_ + k0 + t];
    __syncthreads();
    const int p0 = t, p1 = t + 256;
    float a0 = 0.f, a1 = 0.f;
#pragma unroll 4
    for (int k = 0; k < 48; ++k) {
        const float* wrow = Wq + (size_t)(k0 + k) * 512;
        a0 = fmaf(qs[k], __ldg(wrow + p0), a0);
        a1 = fmaf(qs[k], __ldg(wrow + p1), a1);
    }
    if (ks == 0) {
        a0 += __ldg(bq + p0) + __ldg(bh + p0);
        a1 += __ldg(bq + p1) + __ldg(bh + p1);
    }
    atomicAdd(out + b * 512 + p0, a0);
    atomicAdd(out + b * 512 + p1, a1);
}

// ---------------- softmax without max-shift (|s| <= ~9, exp safe in fp32) ----
// k_sum: grid 384, block 256; chunk of 1024 elements. Combines the 4 N-slice
// partials, computes exp, writes g_e, accumulates per-graph sums.
__global__ void __launch_bounds__(256) k_sum(
    const float* __restrict__ part, float* __restrict__ ebuf,
    const int* __restrict__ gidN, const int* __restrict__ gidE,
    float* __restrict__ gsum) {
    __shared__ float ssum[128];
    const int t = threadIdx.x;
    if (t < 128) ssum[t] = 0.f;
    __syncthreads();
    const int base = blockIdx.x * 1024;
    const bool isNode = base < TN_;          // chunks never straddle TN_ (128*1024)
    const int* gid = isNode ? gidN : gidE;
    const int lofs = isNode ? 0 : TN_;
    const int goff = isNode ? 0 : 64;
#pragma unroll
    for (int jj = 0; jj < 4; ++jj) {
        const int i = base + jj * 256 + t;
        float v = __ldg(part + i)
                + __ldg(part + TT_ + i)
                + __ldg(part + 2 * TT_ + i)
                + __ldg(part + 3 * TT_ + i);
        float e = __expf(v);
        ebuf[i] = e;
        atomicAdd(&ssum[goff + __ldg(gid + i - lofs)], e);
    }
    __syncthreads();
    if (t < 128 && ssum[t] != 0.f) atomicAdd(&gsum[t], ssum[t]);
}

// k_norm: out[i] = e[i] / gsum[graph]
__global__ void __launch_bounds__(256) k_norm(
    const float* __restrict__ ebuf,
    const int* __restrict__ gidN, const int* __restrict__ gidE,
    const float* __restrict__ gsum, float* __restrict__ out) {
    const int base = blockIdx.x * 1024;
    const bool isNode = base < TN_;
    const int* gid = isNode ? gidN : gidE;
    const int lofs = isNode ? 0 : TN_;
    const int goff = isNode ? 0 : 64;
    const int t = threadIdx.x;
#pragma unroll
    for (int jj = 0; jj < 4; ++jj) {
        const int i = base + jj * 256 + t;
        const int g = goff + __ldg(gid + i - lofs);
        out[i] = __ldg(ebuf + i) / __ldg(gsum + g);
    }
}

// ---------------- launch ----------------
extern "C" void kernel_launch(void* const* d_in, const int* in_sizes, int n_in,
                              void* d_out, int out_size) {
    const float* question = (const float*)d_in[0];
    const float* nodes    = (const float*)d_in[1];
    const float* edges    = (const float*)d_in[2];
    const float* W_nq     = (const float*)d_in[3];
    const float* b_nq     = (const float*)d_in[4];
    const float* W_n      = (const float*)d_in[5];
    const float* b_n      = (const float*)d_in[6];
    const float* w_nv     = (const float*)d_in[7];
    // d_in[8] = b_nv — softmax shift-invariant, unused
    const float* W_eq     = (const float*)d_in[9];
    const float* b_eq     = (const float*)d_in[10];
    const float* W_e      = (const float*)d_in[11];
    const float* b_e      = (const float*)d_in[12];
    const float* w_ev     = (const float*)d_in[13];
    // d_in[14] = b_ev — unused
    const int* node_gid   = (const int*)d_in[15];
    const int* edge_gid   = (const int*)d_in[16];
    float* out = (float*)d_out;

    float *qn, *qe, *part, *ebuf, *gsum;
    __nv_bfloat16 *wtn, *wte;
    cudaGetSymbolAddress((void**)&qn,   g_qn);
    cudaGetSymbolAddress((void**)&qe,   g_qe);
    cudaGetSymbolAddress((void**)&wtn,  g_wtn);
    cudaGetSymbolAddress((void**)&wte,  g_wte);
    cudaGetSymbolAddress((void**)&part, g_part);
    cudaGetSymbolAddress((void**)&ebuf, g_e);
    cudaGetSymbolAddress((void**)&gsum, g_sum);

    cudaFuncSetAttribute(k_main, cudaFuncAttributeMaxDynamicSharedMemorySize, SMEM_BYTES);

    k_prep<<<545, 256>>>(W_n, W_e, wtn, wte, qn, qe, gsum);
    k_qproj<<<dim3(B_, 16, 2), 256>>>(question,
                                      W_nq, b_nq, b_n,
                                      W_eq, b_eq, b_e, qn, qe);

    k_main<<<dim3(4, NYN + TE_ / 256), 256, SMEM_BYTES>>>(
        nodes, edges, node_gid, edge_gid, wtn, wte, qn, qe, w_nv, w_ev, part);

    k_sum<<<TT_ / 1024, 256>>>(part, ebuf, node_gid, edge_gid, gsum);
    k_norm<<<TT_ / 1024, 256>>>(ebuf, node_gid, edge_gid, gsum, out);
}

// round 13
// speedup vs baseline: 1.0416x; 1.0416x over previous
#include <cuda_runtime.h>
#include <cuda_bf16.h>
#include <cstdint>

#define DINLINE __device__ __forceinline__

// ---------------- problem sizes ----------------
#define B_  64
#define TN_ 131072
#define TE_ 262144
#define TT_ (TN_ + TE_)
#define QD_ 768
#define PD_ 512
#define KD_ 512

// ---------------- device scratch ----------------
__device__ float g_qn[B_ * PD_];
__device__ float g_qe[B_ * PD_];
__device__ __nv_bfloat16 g_wtn[PD_ * KD_];   // W_n transposed [P][K], bf16
__device__ __nv_bfloat16 g_wte[PD_ * KD_];
__device__ float g_part[4 * TT_];            // per-N-slice partial sums (no init needed)
__device__ float g_e[TT_];                   // exp(score)
__device__ float g_sum[128];                 // per-graph exp sums (0..63 nodes, 64..127 edges)

// ---------------- helpers ----------------
DINLINE void cp16(uint32_t s, const void* g) {
    asm volatile("cp.async.cg.shared.global [%0], [%1], 16;"
                 :: "r"(s), "l"(g) : "memory");
}
DINLINE void cp_commit() { asm volatile("cp.async.commit_group;" ::: "memory"); }
template<int N> DINLINE void cp_wait() {
    asm volatile("cp.async.wait_group %0;" :: "n"(N) : "memory");
}

DINLINE uint32_t smem_u32(const void* p) {
    uint32_t a;
    asm("{ .reg .u64 t; cvta.to.shared.u64 t, %1; cvt.u32.u64 %0, t; }"
        : "=r"(a) : "l"(p));
    return a;
}

DINLINE float tanh_fast(float x) {
    float y;
    asm("tanh.approx.f32 %0, %1;" : "=f"(y) : "f"(x));
    return y;
}

DINLINE void mma_bf16(float* c, const uint32_t* a, const uint32_t* b) {
    asm volatile(
        "mma.sync.aligned.m16n8k16.row.col.f32.bf16.bf16.f32 "
        "{%0,%1,%2,%3}, {%4,%5,%6,%7}, {%8,%9}, {%0,%1,%2,%3};"
        : "+f"(c[0]), "+f"(c[1]), "+f"(c[2]), "+f"(c[3])
        : "r"(a[0]), "r"(a[1]), "r"(a[2]), "r"(a[3]),
          "r"(b[0]), "r"(b[1]));
}

DINLINE void ldm_x4(uint32_t& r0, uint32_t& r1, uint32_t& r2, uint32_t& r3,
                    uint32_t addr) {
    asm volatile("ldmatrix.sync.aligned.m8n8.x4.shared.b16 {%0,%1,%2,%3}, [%4];"
                 : "=r"(r0), "=r"(r1), "=r"(r2), "=r"(r3) : "r"(addr));
}

DINLINE uint32_t pack_bf16x2(float lo, float hi) {
    __nv_bfloat162 v = __float22bfloat162_rn(make_float2(lo, hi));
    return *reinterpret_cast<uint32_t*>(&v);
}

// ---------------- main fused GEMM ----------------
// CTA: 256 threads (8 warps, 4 wm x 2 wn, warp tile 64x64).
// Tile: M=256, N=128 (blockIdx.x in 0..3), K=512 in 16 chunks of 32.
// blockIdx.y in [0,1536): y<512 -> nodes; else edges.
// SMEM (bf16, 80B padded rows):
//   A: 2 x (256 x 80B = 20480)  @ 0
//   B: 3 x (128 x 80B = 10240)  @ 40960
//   s_sm: 256 floats            @ 71680
#define ROWB   80u
#define ATILE  20480u
#define BTILE  10240u
#define BOFF   40960u
#define SM_OFF 71680u
#define SMEM_BYTES (71680 + 1024)
#define NYN 512              // node tiles in y

__global__ void __launch_bounds__(256, 1) k_main(
    const float* __restrict__ An, const float* __restrict__ Ae,
    const int* __restrict__ gidN, const int* __restrict__ gidE,
    const __nv_bfloat16* __restrict__ WtN, const __nv_bfloat16* __restrict__ WtE,
    const float* __restrict__ qN, const float* __restrict__ qE,
    const float* __restrict__ wvN, const float* __restrict__ wvE,
    float* __restrict__ part)
{
    extern __shared__ char smem[];
    float* s_sm = reinterpret_cast<float*>(smem + SM_OFF);

    const bool isNode = blockIdx.y < NYN;
    const int  ty     = isNode ? blockIdx.y : blockIdx.y - NYN;
    const float* __restrict__ A    = isNode ? An   : Ae;
    const int*   __restrict__ gid  = isNode ? gidN : gidE;
    const __nv_bfloat16* __restrict__ Wt = isNode ? WtN : WtE;
    const float* __restrict__ qeff = isNode ? qN   : qE;
    const float* __restrict__ wv   = isNode ? wvN  : wvE;
    const int    sOff = isNode ? 0 : TN_;

    const int tid  = threadIdx.x;
    const int lane = tid & 31;
    const int warp = tid >> 5;
    const int wm   = warp & 3;   // M block of 64
    const int wn   = warp >> 2;  // N block of 64

    const int mBase = ty * 256;
    const int nBase = blockIdx.x * 128;

    const uint32_t sb = smem_u32(smem);

    s_sm[tid] = 0.f;

    // ---- A loader: 256 rows x 32 f32 per chunk; thread: 8 float4
    const int aRow = tid >> 3;
    const int aQ   = tid & 7;
    const float* Abase = A + (size_t)(mBase + aRow) * KD_ + aQ * 4;

    float4 ra[8];
    auto ldA = [&](int kc) {
        const float* p = Abase + kc * 32;
#pragma unroll
        for (int i = 0; i < 8; ++i)
            ra[i] = *reinterpret_cast<const float4*>(p + (size_t)i * 32 * KD_);
    };
    auto stsA = [&](int buf) {
        const uint32_t base = sb + buf * ATILE + aRow * ROWB + aQ * 8;
#pragma unroll
        for (int i = 0; i < 8; ++i) {
            uint32_t lo = pack_bf16x2(ra[i].x, ra[i].y);
            uint32_t hi = pack_bf16x2(ra[i].z, ra[i].w);
            asm volatile("st.shared.v2.b32 [%0], {%1,%2};"
                         :: "r"(base + i * 32 * ROWB), "r"(lo), "r"(hi) : "memory");
        }
    };
    // B: 128 n-rows x 32 bf16 per chunk = 8KB = 512 x 16B; thread does 2 cp16
    const int bIdx0 = tid * 2;
    auto cpB = [&](int slot, int kc) {
#pragma unroll
        for (int j = 0; j < 2; ++j) {
            int idx = bIdx0 + j;
            int n = idx >> 2, g = idx & 3;
            cp16(sb + BOFF + slot * BTILE + n * ROWB + g * 16,
                 Wt + (size_t)(nBase + n) * KD_ + kc * 32 + g * 8);
        }
        cp_commit();
    };

    float c[4][8][4];
#pragma unroll
    for (int mt = 0; mt < 4; ++mt)
#pragma unroll
        for (int nt = 0; nt < 8; ++nt)
#pragma unroll
            for (int i = 0; i < 4; ++i) c[mt][nt][i] = 0.f;

    // ---- ldmatrix per-lane offsets ----
    const int j = lane >> 3;
    const uint32_t aLane = (uint32_t)(wm * 64 + ((j & 1) << 3) + (lane & 7)) * ROWB
                         + (uint32_t)(j >> 1) * 16u;
    const uint32_t bLane = (uint32_t)(wn * 64 + ((j >> 1) << 3) + (lane & 7)) * ROWB
                         + (uint32_t)(j & 1) * 16u;

    // ---- register-resident A fragment sets (ping-pong, no copies) ----
    uint32_t aF0[4][4], aF1[4][4];

    auto ldA_frags = [&](uint32_t aT2, uint32_t ko, uint32_t (&a)[4][4]) {
#pragma unroll
        for (int mt = 0; mt < 4; ++mt)
            ldm_x4(a[mt][0], a[mt][1], a[mt][2], a[mt][3],
                   aT2 + mt * 16 * ROWB + ko);
    };

    auto phase = [&](const uint32_t (&aIn)[4][4], uint32_t (&aOut)[4][4],
                     uint32_t bT2, uint32_t ko,
                     uint32_t aT2n, uint32_t kon, bool preloadA) {
        uint32_t b[2][2][2];   // [buf][nt-in-pair][frag]
        ldm_x4(b[0][0][0], b[0][0][1], b[0][1][0], b[0][1][1], bT2 + ko);
#pragma unroll
        for (int p = 0; p < 4; ++p) {
            const int cb = p & 1, nb = cb ^ 1;
            if (p < 3) {
                ldm_x4(b[nb][0][0], b[nb][0][1], b[nb][1][0], b[nb][1][1],
                       bT2 + (uint32_t)(p + 1) * 16 * ROWB + ko);
            } else if (preloadA) {
                ldA_frags(aT2n, kon, aOut);
            }
#pragma unroll
            for (int mt = 0; mt < 4; ++mt) {
                mma_bf16(c[mt][2 * p],     aIn[mt], b[cb][0]);
                mma_bf16(c[mt][2 * p + 1], aIn[mt], b[cb][1]);
            }
        }
    };

    // ---- preamble ----
    ldA(0);
    cpB(0, 0);
    cpB(1, 1);
    stsA(0);
    ldA(1);
    cp_wait<1>();
    __syncthreads();
    ldA_frags(sb + aLane, 0, aF0);     // chunk 0, ks=0

#pragma unroll 1
    for (int kc = 0; kc < 16; ++kc) {
        const int abuf = kc & 1;
        if (kc + 2 < 16) cpB((kc + 2) % 3, kc + 2);

        const uint32_t aT2 = sb + abuf * ATILE + aLane;
        const uint32_t bT2 = sb + BOFF + (kc % 3) * BTILE + bLane;

        phase(aF0, aF1, bT2, 0, aT2, 32, true);
        if (kc + 1 < 16) stsA(abuf ^ 1);
        if (kc + 2 < 16) ldA(kc + 2);
        phase(aF1, aF0, bT2, 32, 0, 0, false);

        if (kc + 2 < 16) cp_wait<1>(); else cp_wait<0>();
        __syncthreads();
        if (kc + 1 < 16)
            ldA_frags(sb + (abuf ^ 1) * ATILE + aLane, 0, aF0);
    }

    // ---- epilogue: partial s[m] for this N-slice; no global atomics ----
    const int n0 = wn * 64 + 2 * (lane & 3);
#pragma unroll
    for (int mt = 0; mt < 4; ++mt) {
#pragma unroll
        for (int h = 0; h < 2; ++h) {
            const int row = wm * 64 + mt * 16 + (lane >> 2) + h * 8;
            const int g = __ldg(gid + mBase + row);
            const float* qrow = qeff + (size_t)g * PD_ + nBase;
            float s = 0.f;
#pragma unroll
            for (int nt = 0; nt < 8; ++nt) {
                const int nn = n0 + nt * 8;
                float2 q2 = *reinterpret_cast<const float2*>(qrow + nn);
                float2 w2 = *reinterpret_cast<const float2*>(wv + nBase + nn);
                float x0 = tanh_fast(c[mt][nt][h * 2 + 0] + q2.x);
                float x1 = tanh_fast(c[mt][nt][h * 2 + 1] + q2.y);
                s = fmaf(x0, w2.x, s);
                s = fmaf(x1, w2.y, s);
            }
            s += __shfl_xor_sync(0xffffffffu, s, 1);
            s += __shfl_xor_sync(0xffffffffu, s, 2);
            if ((lane & 3) == 0) atomicAdd(&s_sm[row], s);
        }
    }
    __syncthreads();
    part[(size_t)blockIdx.x * TT_ + sOff + mBase + tid] = s_sm[tid];
}

// ---------------- prep: transposes + qn/qe/gsum zeroing, one launch ----------------
__global__ void __launch_bounds__(256) k_prep(
    const float* __restrict__ Wn, const float* __restrict__ We,
    __nv_bfloat16* __restrict__ WtN, __nv_bfloat16* __restrict__ WtE,
    float* __restrict__ qn, float* __restrict__ qe, float* __restrict__ gsum) {
    const int blk = blockIdx.x;
    const int t = threadIdx.x;
    if (blk == 544) {
        if (t < 128) gsum[t] = 0.f;
        return;
    }
    if (blk >= 512) {
        const int zi = blk - 512;                 // 0..31
        float* dst = (zi < 16) ? (qn + zi * 2048) : (qe + (zi - 16) * 2048);
#pragma unroll
        for (int k = 0; k < 8; ++k) dst[k * 256 + t] = 0.f;
        return;
    }
    const bool isE = blk >= 256;
    const int b2 = blk & 255;
    const float* W = isE ? We : Wn;
    __nv_bfloat16* Wt = isE ? WtE : WtN;
    __shared__ float tile[32][33];
    const int tx = t & 31, ty2 = t >> 5;          // 32 x 8
    int x = (b2 & 15) * 32 + tx;                  // p
    int y = (b2 >> 4) * 32 + ty2;                 // k
#pragma unroll
    for (int j = 0; j < 32; j += 8)
        tile[ty2 + j][tx] = W[(y + j) * 512 + x];
    __syncthreads();
    int xo = (b2 >> 4) * 32 + tx;                 // k
    int yo = (b2 & 15) * 32 + ty2;                // p
#pragma unroll
    for (int j = 0; j < 32; j += 8)
        Wt[(yo + j) * 512 + xo] = __float2bfloat16(tile[tx][ty2 + j]);
}

// split-k qproj, grid (B_, 16, 2): k-slice 48; z selects node/edge weights.
__global__ void __launch_bounds__(256) k_qproj(
    const float* __restrict__ q,
    const float* __restrict__ WqN, const float* __restrict__ bqN, const float* __restrict__ bhN,
    const float* __restrict__ WqE, const float* __restrict__ bqE, const float* __restrict__ bhE,
    float* __restrict__ outN, float* __restrict__ outE) {
    const float* Wq = blockIdx.z ? WqE : WqN;
    const float* bq = blockIdx.z ? bqE : bqN;
    const float* bh = blockIdx.z ? bhE : bhN;
    float* out = blockIdx.z ? outE : outN;
    __shared__ float qs[48];
    const int b = blockIdx.x, ks = blockIdx.y;
    const int k0 = ks * 48;
    const int t = threadIdx.x;
    if (t < 48) qs[t] = q[b * QD_ + k0 + t];
    __syncthreads();
    const int p0 = t, p1 = t + 256;
    float a0 = 0.f, a1 = 0.f;
#pragma unroll 4
    for (int k = 0; k < 48; ++k) {
        const float* wrow = Wq + (size_t)(k0 + k) * 512;
        a0 = fmaf(qs[k], __ldg(wrow + p0), a0);
        a1 = fmaf(qs[k], __ldg(wrow + p1), a1);
    }
    if (ks == 0) {
        a0 += __ldg(bq + p0) + __ldg(bh + p0);
        a1 += __ldg(bq + p1) + __ldg(bh + p1);
    }
    atomicAdd(out + b * 512 + p0, a0);
    atomicAdd(out + b * 512 + p1, a1);
}

// ---------------- softmax without max-shift (|s| <= ~9, exp safe in fp32) ----
// k_sum: warp-uniform segment reduction — sorted gids mean nearly every warp
// sees ONE graph id; butterfly-reduce and issue 1 smem atomic per warp.
__global__ void __launch_bounds__(256) k_sum(
    const float* __restrict__ part, float* __restrict__ ebuf,
    const int* __restrict__ gidN, const int* __restrict__ gidE,
    float* __restrict__ gsum) {
    __shared__ float ssum[128];
    const int t = threadIdx.x;
    if (t < 128) ssum[t] = 0.f;
    __syncthreads();
    const int base = blockIdx.x * 1024;
    const bool isNode = base < TN_;          // chunks never straddle TN_ (128*1024)
    const int* gid = isNode ? gidN : gidE;
    const int lofs = isNode ? 0 : TN_;
    const int goff = isNode ? 0 : 64;
#pragma unroll
    for (int jj = 0; jj < 4; ++jj) {
        const int i = base + jj * 256 + t;
        float v = __ldg(part + i)
                + __ldg(part + TT_ + i)
                + __ldg(part + 2 * TT_ + i)
                + __ldg(part + 3 * TT_ + i);
        float e = __expf(v);
        ebuf[i] = e;
        const int g = __ldg(gid + i - lofs);
        const int g0 = __shfl_sync(0xffffffffu, g, 0);
        if (__all_sync(0xffffffffu, g == g0)) {
            float r = e;
            r += __shfl_xor_sync(0xffffffffu, r, 16);
            r += __shfl_xor_sync(0xffffffffu, r, 8);
            r += __shfl_xor_sync(0xffffffffu, r, 4);
            r += __shfl_xor_sync(0xffffffffu, r, 2);
            r += __shfl_xor_sync(0xffffffffu, r, 1);
            if ((t & 31) == 0) atomicAdd(&ssum[goff + g0], r);
        } else {
            atomicAdd(&ssum[goff + g], e);
        }
    }
    __syncthreads();
    if (t < 128 && ssum[t] != 0.f) atomicAdd(&gsum[t], ssum[t]);
}

// k_norm: out[i] = e[i] / gsum[graph]
__global__ void __launch_bounds__(256) k_norm(
    const float* __restrict__ ebuf,
    const int* __restrict__ gidN, const int* __restrict__ gidE,
    const float* __restrict__ gsum, float* __restrict__ out) {
    const int base = blockIdx.x * 1024;
    const bool isNode = base < TN_;
    const int* gid = isNode ? gidN : gidE;
    const int lofs = isNode ? 0 : TN_;
    const int goff = isNode ? 0 : 64;
    const int t = threadIdx.x;
#pragma unroll
    for (int jj = 0; jj < 4; ++jj) {
        const int i = base + jj * 256 + t;
        const int g = goff + __ldg(gid + i - lofs);
        out[i] = __ldg(ebuf + i) / __ldg(gsum + g);
    }
}

// ---------------- launch ----------------
extern "C" void kernel_launch(void* const* d_in, const int* in_sizes, int n_in,
                              void* d_out, int out_size) {
    const float* question = (const float*)d_in[0];
    const float* nodes    = (const float*)d_in[1];
    const float* edges    = (const float*)d_in[2];
    const float* W_nq     = (const float*)d_in[3];
    const float* b_nq     = (const float*)d_in[4];
    const float* W_n      = (const float*)d_in[5];
    const float* b_n      = (const float*)d_in[6];
    const float* w_nv     = (const float*)d_in[7];
    // d_in[8] = b_nv — softmax shift-invariant, unused
    const float* W_eq     = (const float*)d_in[9];
    const float* b_eq     = (const float*)d_in[10];
    const float* W_e      = (const float*)d_in[11];
    const float* b_e      = (const float*)d_in[12];
    const float* w_ev     = (const float*)d_in[13];
    // d_in[14] = b_ev — unused
    const int* node_gid   = (const int*)d_in[15];
    const int* edge_gid   = (const int*)d_in[16];
    float* out = (float*)d_out;

    float *qn, *qe, *part, *ebuf, *gsum;
    __nv_bfloat16 *wtn, *wte;
    cudaGetSymbolAddress((void**)&qn,   g_qn);
    cudaGetSymbolAddress((void**)&qe,   g_qe);
    cudaGetSymbolAddress((void**)&wtn,  g_wtn);
    cudaGetSymbolAddress((void**)&wte,  g_wte);
    cudaGetSymbolAddress((void**)&part, g_part);
    cudaGetSymbolAddress((void**)&ebuf, g_e);
    cudaGetSymbolAddress((void**)&gsum, g_sum);

    cudaFuncSetAttribute(k_main, cudaFuncAttributeMaxDynamicSharedMemorySize, SMEM_BYTES);

    k_prep<<<545, 256>>>(W_n, W_e, wtn, wte, qn, qe, gsum);
    k_qproj<<<dim3(B_, 16, 2), 256>>>(question,
                                      W_nq, b_nq, b_n,
                                      W_eq, b_eq, b_e, qn, qe);

    k_main<<<dim3(4, NYN + TE_ / 256), 256, SMEM_BYTES>>>(
        nodes, edges, node_gid, edge_gid, wtn, wte, qn, qe, w_nv, w_ev, part);

    k_sum<<<TT_ / 1024, 256>>>(part, ebuf, node_gid, edge_gid, gsum);
    k_norm<<<TT_ / 1024, 256>>>(ebuf, node_gid, edge_gid, gsum, out);
}

// round 14
// speedup vs baseline: 1.0453x; 1.0035x over previous
#include <cuda_runtime.h>
#include <cuda_bf16.h>
#include <cstdint>

#define DINLINE __device__ __forceinline__

// ---------------- problem sizes ----------------
#define B_  64
#define TN_ 131072
#define TE_ 262144
#define TT_ (TN_ + TE_)
#define QD_ 768
#define PD_ 512
#define KD_ 512

// ---------------- device scratch ----------------
__device__ float g_qn[B_ * PD_];
__device__ float g_qe[B_ * PD_];
__device__ __nv_bfloat16 g_wtn[PD_ * KD_];   // W_n transposed [P][K], bf16
__device__ __nv_bfloat16 g_wte[PD_ * KD_];
__device__ float g_part[4 * TT_];            // per-N-slice partial sums (no init needed)
__device__ float g_sum[128];                 // per-graph exp sums (0..63 nodes, 64..127 edges)
__device__ int   g_ctr;                      // spin-barrier counter

// ---------------- helpers ----------------
DINLINE void cp16(uint32_t s, const void* g) {
    asm volatile("cp.async.cg.shared.global [%0], [%1], 16;"
                 :: "r"(s), "l"(g) : "memory");
}
DINLINE void cp_commit() { asm volatile("cp.async.commit_group;" ::: "memory"); }
template<int N> DINLINE void cp_wait() {
    asm volatile("cp.async.wait_group %0;" :: "n"(N) : "memory");
}

DINLINE uint32_t smem_u32(const void* p) {
    uint32_t a;
    asm("{ .reg .u64 t; cvta.to.shared.u64 t, %1; cvt.u32.u64 %0, t; }"
        : "=r"(a) : "l"(p));
    return a;
}

DINLINE float tanh_fast(float x) {
    float y;
    asm("tanh.approx.f32 %0, %1;" : "=f"(y) : "f"(x));
    return y;
}

DINLINE void mma_bf16(float* c, const uint32_t* a, const uint32_t* b) {
    asm volatile(
        "mma.sync.aligned.m16n8k16.row.col.f32.bf16.bf16.f32 "
        "{%0,%1,%2,%3}, {%4,%5,%6,%7}, {%8,%9}, {%0,%1,%2,%3};"
        : "+f"(c[0]), "+f"(c[1]), "+f"(c[2]), "+f"(c[3])
        : "r"(a[0]), "r"(a[1]), "r"(a[2]), "r"(a[3]),
          "r"(b[0]), "r"(b[1]));
}

DINLINE void ldm_x4(uint32_t& r0, uint32_t& r1, uint32_t& r2, uint32_t& r3,
                    uint32_t addr) {
    asm volatile("ldmatrix.sync.aligned.m8n8.x4.shared.b16 {%0,%1,%2,%3}, [%4];"
                 : "=r"(r0), "=r"(r1), "=r"(r2), "=r"(r3) : "r"(addr));
}

DINLINE uint32_t pack_bf16x2(float lo, float hi) {
    __nv_bfloat162 v = __float22bfloat162_rn(make_float2(lo, hi));
    return *reinterpret_cast<uint32_t*>(&v);
}

// ---------------- main fused GEMM ----------------
// CTA: 256 threads (8 warps, 4 wm x 2 wn, warp tile 64x64).
// Tile: M=256, N=128 (blockIdx.x in 0..3), K=512 in 16 chunks of 32.
// blockIdx.y in [0,1536): y<512 -> nodes; else edges.
// SMEM (bf16, 80B padded rows):
//   A: 2 x (256 x 80B = 20480)  @ 0
//   B: 3 x (128 x 80B = 10240)  @ 40960
//   s_sm: 256 floats            @ 71680
#define ROWB   80u
#define ATILE  20480u
#define BTILE  10240u
#define BOFF   40960u
#define SM_OFF 71680u
#define SMEM_BYTES (71680 + 1024)
#define NYN 512              // node tiles in y

__global__ void __launch_bounds__(256, 1) k_main(
    const float* __restrict__ An, const float* __restrict__ Ae,
    const int* __restrict__ gidN, const int* __restrict__ gidE,
    const __nv_bfloat16* __restrict__ WtN, const __nv_bfloat16* __restrict__ WtE,
    const float* __restrict__ qN, const float* __restrict__ qE,
    const float* __restrict__ wvN, const float* __restrict__ wvE,
    float* __restrict__ part)
{
    extern __shared__ char smem[];
    float* s_sm = reinterpret_cast<float*>(smem + SM_OFF);

    const bool isNode = blockIdx.y < NYN;
    const int  ty     = isNode ? blockIdx.y : blockIdx.y - NYN;
    const float* __restrict__ A    = isNode ? An   : Ae;
    const int*   __restrict__ gid  = isNode ? gidN : gidE;
    const __nv_bfloat16* __restrict__ Wt = isNode ? WtN : WtE;
    const float* __restrict__ qeff = isNode ? qN   : qE;
    const float* __restrict__ wv   = isNode ? wvN  : wvE;
    const int    sOff = isNode ? 0 : TN_;

    const int tid  = threadIdx.x;
    const int lane = tid & 31;
    const int warp = tid >> 5;
    const int wm   = warp & 3;   // M block of 64
    const int wn   = warp >> 2;  // N block of 64

    const int mBase = ty * 256;
    const int nBase = blockIdx.x * 128;

    const uint32_t sb = smem_u32(smem);

    s_sm[tid] = 0.f;

    // ---- A loader: 256 rows x 32 f32 per chunk; thread: 8 float4
    const int aRow = tid >> 3;
    const int aQ   = tid & 7;
    const float* Abase = A + (size_t)(mBase + aRow) * KD_ + aQ * 4;

    float4 ra[8];
    auto ldA = [&](int kc) {
        const float* p = Abase + kc * 32;
#pragma unroll
        for (int i = 0; i < 8; ++i)
            ra[i] = *reinterpret_cast<const float4*>(p + (size_t)i * 32 * KD_);
    };
    auto stsA = [&](int buf) {
        const uint32_t base = sb + buf * ATILE + aRow * ROWB + aQ * 8;
#pragma unroll
        for (int i = 0; i < 8; ++i) {
            uint32_t lo = pack_bf16x2(ra[i].x, ra[i].y);
            uint32_t hi = pack_bf16x2(ra[i].z, ra[i].w);
            asm volatile("st.shared.v2.b32 [%0], {%1,%2};"
                         :: "r"(base + i * 32 * ROWB), "r"(lo), "r"(hi) : "memory");
        }
    };
    // B: 128 n-rows x 32 bf16 per chunk = 8KB = 512 x 16B; thread does 2 cp16
    const int bIdx0 = tid * 2;
    auto cpB = [&](int slot, int kc) {
#pragma unroll
        for (int j = 0; j < 2; ++j) {
            int idx = bIdx0 + j;
            int n = idx >> 2, g = idx & 3;
            cp16(sb + BOFF + slot * BTILE + n * ROWB + g * 16,
                 Wt + (size_t)(nBase + n) * KD_ + kc * 32 + g * 8);
        }
        cp_commit();
    };

    float c[4][8][4];
#pragma unroll
    for (int mt = 0; mt < 4; ++mt)
#pragma unroll
        for (int nt = 0; nt < 8; ++nt)
#pragma unroll
            for (int i = 0; i < 4; ++i) c[mt][nt][i] = 0.f;

    // ---- ldmatrix per-lane offsets ----
    const int j = lane >> 3;
    const uint32_t aLane = (uint32_t)(wm * 64 + ((j & 1) << 3) + (lane & 7)) * ROWB
                         + (uint32_t)(j >> 1) * 16u;
    const uint32_t bLane = (uint32_t)(wn * 64 + ((j >> 1) << 3) + (lane & 7)) * ROWB
                         + (uint32_t)(j & 1) * 16u;

    // ---- register-resident A fragment sets (ping-pong, no copies) ----
    uint32_t aF0[4][4], aF1[4][4];

    auto ldA_frags = [&](uint32_t aT2, uint32_t ko, uint32_t (&a)[4][4]) {
#pragma unroll
        for (int mt = 0; mt < 4; ++mt)
            ldm_x4(a[mt][0], a[mt][1], a[mt][2], a[mt][3],
                   aT2 + mt * 16 * ROWB + ko);
    };

    auto phase = [&](const uint32_t (&aIn)[4][4], uint32_t (&aOut)[4][4],
                     uint32_t bT2, uint32_t ko,
                     uint32_t aT2n, uint32_t kon, bool preloadA) {
        uint32_t b[2][2][2];   // [buf][nt-in-pair][frag]
        ldm_x4(b[0][0][0], b[0][0][1], b[0][1][0], b[0][1][1], bT2 + ko);
#pragma unroll
        for (int p = 0; p < 4; ++p) {
            const int cb = p & 1, nb = cb ^ 1;
            if (p < 3) {
                ldm_x4(b[nb][0][0], b[nb][0][1], b[nb][1][0], b[nb][1][1],
                       bT2 + (uint32_t)(p + 1) * 16 * ROWB + ko);
            } else if (preloadA) {
                ldA_frags(aT2n, kon, aOut);
            }
#pragma unroll
            for (int mt = 0; mt < 4; ++mt) {
                mma_bf16(c[mt][2 * p],     aIn[mt], b[cb][0]);
                mma_bf16(c[mt][2 * p + 1], aIn[mt], b[cb][1]);
            }
        }
    };

    // ---- preamble ----
    ldA(0);
    cpB(0, 0);
    cpB(1, 1);
    stsA(0);
    ldA(1);
    cp_wait<1>();
    __syncthreads();
    ldA_frags(sb + aLane, 0, aF0);     // chunk 0, ks=0

#pragma unroll 1
    for (int kc = 0; kc < 16; ++kc) {
        const int abuf = kc & 1;
        if (kc + 2 < 16) cpB((kc + 2) % 3, kc + 2);

        const uint32_t aT2 = sb + abuf * ATILE + aLane;
        const uint32_t bT2 = sb + BOFF + (kc % 3) * BTILE + bLane;

        phase(aF0, aF1, bT2, 0, aT2, 32, true);
        if (kc + 1 < 16) stsA(abuf ^ 1);
        if (kc + 2 < 16) ldA(kc + 2);
        phase(aF1, aF0, bT2, 32, 0, 0, false);

        if (kc + 2 < 16) cp_wait<1>(); else cp_wait<0>();
        __syncthreads();
        if (kc + 1 < 16)
            ldA_frags(sb + (abuf ^ 1) * ATILE + aLane, 0, aF0);
    }

    // ---- epilogue: partial s[m] for this N-slice; no global atomics ----
    const int n0 = wn * 64 + 2 * (lane & 3);
#pragma unroll
    for (int mt = 0; mt < 4; ++mt) {
#pragma unroll
        for (int h = 0; h < 2; ++h) {
            const int row = wm * 64 + mt * 16 + (lane >> 2) + h * 8;
            const int g = __ldg(gid + mBase + row);
            const float* qrow = qeff + (size_t)g * PD_ + nBase;
            float s = 0.f;
#pragma unroll
            for (int nt = 0; nt < 8; ++nt) {
                const int nn = n0 + nt * 8;
                float2 q2 = *reinterpret_cast<const float2*>(qrow + nn);
                float2 w2 = *reinterpret_cast<const float2*>(wv + nBase + nn);
                float x0 = tanh_fast(c[mt][nt][h * 2 + 0] + q2.x);
                float x1 = tanh_fast(c[mt][nt][h * 2 + 1] + q2.y);
                s = fmaf(x0, w2.x, s);
                s = fmaf(x1, w2.y, s);
            }
            s += __shfl_xor_sync(0xffffffffu, s, 1);
            s += __shfl_xor_sync(0xffffffffu, s, 2);
            if ((lane & 3) == 0) atomicAdd(&s_sm[row], s);
        }
    }
    __syncthreads();
    part[(size_t)blockIdx.x * TT_ + sOff + mBase + tid] = s_sm[tid];
}

// ---------------- prep: transposes + qn/qe/gsum/ctr zeroing, one launch ----------------
__global__ void __launch_bounds__(256) k_prep(
    const float* __restrict__ Wn, const float* __restrict__ We,
    __nv_bfloat16* __restrict__ WtN, __nv_bfloat16* __restrict__ WtE,
    float* __restrict__ qn, float* __restrict__ qe,
    float* __restrict__ gsum, int* __restrict__ ctr) {
    const int blk = blockIdx.x;
    const int t = threadIdx.x;
    if (blk == 544) {
        if (t < 128) gsum[t] = 0.f;
        if (t == 128) *ctr = 0;
        return;
    }
    if (blk >= 512) {
        const int zi = blk - 512;                 // 0..31
        float* dst = (zi < 16) ? (qn + zi * 2048) : (qe + (zi - 16) * 2048);
#pragma unroll
        for (int k = 0; k < 8; ++k) dst[k * 256 + t] = 0.f;
        return;
    }
    const bool isE = blk >= 256;
    const int b2 = blk & 255;
    const float* W = isE ? We : Wn;
    __nv_bfloat16* Wt = isE ? WtE : WtN;
    __shared__ float tile[32][33];
    const int tx = t & 31, ty2 = t >> 5;          // 32 x 8
    int x = (b2 & 15) * 32 + tx;                  // p
    int y = (b2 >> 4) * 32 + ty2;                 // k
#pragma unroll
    for (int j = 0; j < 32; j += 8)
        tile[ty2 + j][tx] = W[(y + j) * 512 + x];
    __syncthreads();
    int xo = (b2 >> 4) * 32 + tx;                 // k
    int yo = (b2 & 15) * 32 + ty2;                // p
#pragma unroll
    for (int j = 0; j < 32; j += 8)
        Wt[(yo + j) * 512 + xo] = __float2bfloat16(tile[tx][ty2 + j]);
}

// split-k qproj, grid (B_, 16, 2): k-slice 48; z selects node/edge weights.
__global__ void __launch_bounds__(256) k_qproj(
    const float* __restrict__ q,
    const float* __restrict__ WqN, const float* __restrict__ bqN, const float* __restrict__ bhN,
    const float* __restrict__ WqE, const float* __restrict__ bqE, const float* __restrict__ bhE,
    float* __restrict__ outN, float* __restrict__ outE) {
    const float* Wq = blockIdx.z ? WqE : WqN;
    const float* bq = blockIdx.z ? bqE : bqN;
    const float* bh = blockIdx.z ? bhE : bhN;
    float* out = blockIdx.z ? outE : outN;
    __shared__ float qs[48];
    const int b = blockIdx.x, ks = blockIdx.y;
    const int k0 = ks * 48;
    const int t = threadIdx.x;
    if (t < 48) qs[t] = q[b * QD_ + k0 + t];
    __syncthreads();
    const int p0 = t, p1 = t + 256;
    float a0 = 0.f, a1 = 0.f;
#pragma unroll 4
    for (int k = 0; k < 48; ++k) {
        const float* wrow = Wq + (size_t)(k0 + k) * 512;
        a0 = fmaf(qs[k], __ldg(wrow + p0), a0);
        a1 = fmaf(qs[k], __ldg(wrow + p1), a1);
    }
    if (ks == 0) {
        a0 += __ldg(bq + p0) + __ldg(bh + p0);
        a1 += __ldg(bq + p1) + __ldg(bh + p1);
    }
    atomicAdd(out + b * 512 + p0, a0);
    atomicAdd(out + b * 512 + p1, a1);
}

// ---------------- fused softmax (no max-shift; |s| <= ~9 so exp is fp32-safe) ----
// One kernel, grid 384 (all co-resident: 22 regs, 512B smem -> >=8 blocks/SM).
// Phase 1: combine partials -> e (registers), warp-uniform smem reduce -> gsum.
// Device-wide spin barrier on g_ctr, then normalize from registers.
__global__ void __launch_bounds__(256) k_soft(
    const float* __restrict__ part,
    const int* __restrict__ gidN, const int* __restrict__ gidE,
    float* __restrict__ gsum, int* __restrict__ ctr,
    float* __restrict__ out) {
    __shared__ float ssum[128];
    const int t = threadIdx.x;
    if (t < 128) ssum[t] = 0.f;
    __syncthreads();
    const int base = blockIdx.x * 1024;
    const bool isNode = base < TN_;          // chunks never straddle TN_ (128*1024)
    const int* gid = isNode ? gidN : gidE;
    const int lofs = isNode ? 0 : TN_;
    const int goff = isNode ? 0 : 64;

    float ev[4];
    int   gv[4];
#pragma unroll
    for (int jj = 0; jj < 4; ++jj) {
        const int i = base + jj * 256 + t;
        float v = __ldg(part + i)
                + __ldg(part + TT_ + i)
                + __ldg(part + 2 * TT_ + i)
                + __ldg(part + 3 * TT_ + i);
        float e = __expf(v);
        ev[jj] = e;
        const int g = __ldg(gid + i - lofs);
        gv[jj] = goff + g;
        const int g0 = __shfl_sync(0xffffffffu, g, 0);
        if (__all_sync(0xffffffffu, g == g0)) {
            float r = e;
            r += __shfl_xor_sync(0xffffffffu, r, 16);
            r += __shfl_xor_sync(0xffffffffu, r, 8);
            r += __shfl_xor_sync(0xffffffffu, r, 4);
            r += __shfl_xor_sync(0xffffffffu, r, 2);
            r += __shfl_xor_sync(0xffffffffu, r, 1);
            if ((t & 31) == 0) atomicAdd(&ssum[goff + g0], r);
        } else {
            atomicAdd(&ssum[goff + g], e);
        }
    }
    __syncthreads();
    if (t < 128 && ssum[t] != 0.f) atomicAdd(&gsum[t], ssum[t]);

    // ---- device-wide barrier ----
    __threadfence();
    __syncthreads();
    if (t == 0) {
        atomicAdd(ctr, 1);
        volatile int* vc = ctr;
        while (*vc < (int)gridDim.x) { }
    }
    __syncthreads();
    __threadfence();

    // ---- normalize from registers ----
#pragma unroll
    for (int jj = 0; jj < 4; ++jj) {
        const int i = base + jj * 256 + t;
        float z = __ldcg(gsum + gv[jj]);
        out[i] = __fdividef(ev[jj], z);
    }
}

// ---------------- launch ----------------
extern "C" void kernel_launch(void* const* d_in, const int* in_sizes, int n_in,
                              void* d_out, int out_size) {
    const float* question = (const float*)d_in[0];
    const float* nodes    = (const float*)d_in[1];
    const float* edges    = (const float*)d_in[2];
    const float* W_nq     = (const float*)d_in[3];
    const float* b_nq     = (const float*)d_in[4];
    const float* W_n      = (const float*)d_in[5];
    const float* b_n      = (const float*)d_in[6];
    const float* w_nv     = (const float*)d_in[7];
    // d_in[8] = b_nv — softmax shift-invariant, unused
    const float* W_eq     = (const float*)d_in[9];
    const float* b_eq     = (const float*)d_in[10];
    const float* W_e      = (const float*)d_in[11];
    const float* b_e      = (const float*)d_in[12];
    const float* w_ev     = (const float*)d_in[13];
    // d_in[14] = b_ev — unused
    const int* node_gid   = (const int*)d_in[15];
    const int* edge_gid   = (const int*)d_in[16];
    float* out = (float*)d_out;

    float *qn, *qe, *part, *gsum;
    int* ctr;
    __nv_bfloat16 *wtn, *wte;
    cudaGetSymbolAddress((void**)&qn,   g_qn);
    cudaGetSymbolAddress((void**)&qe,   g_qe);
    cudaGetSymbolAddress((void**)&wtn,  g_wtn);
    cudaGetSymbolAddress((void**)&wte,  g_wte);
    cudaGetSymbolAddress((void**)&part, g_part);
    cudaGetSymbolAddress((void**)&gsum, g_sum);
    cudaGetSymbolAddress((void**)&ctr,  g_ctr);

    cudaFuncSetAttribute(k_main, cudaFuncAttributeMaxDynamicSharedMemorySize, SMEM_BYTES);

    k_prep<<<545, 256>>>(W_n, W_e, wtn, wte, qn, qe, gsum, ctr);
    k_qproj<<<dim3(B_, 16, 2), 256>>>(question,
                                      W_nq, b_nq, b_n,
                                      W_eq, b_eq, b_e, qn, qe);

    k_main<<<dim3(4, NYN + TE_ / 256), 256, SMEM_BYTES>>>(
        nodes, edges, node_gid, edge_gid, wtn, wte, qn, qe, w_nv, w_ev, part);

    k_soft<<<TT_ / 1024, 256>>>(part, node_gid, edge_gid, gsum, ctr, out);
}